// round 5
// baseline (speedup 1.0000x reference)
#include <cuda_runtime.h>

// Problem constants
#define TD     64
#define MODES  16
#define MRI    32          // 2*MODES
#define CIN    64
#define COUT   64
#define PD     16384       // N*D
#define SCOL   1048576     // PD*64 floats per time row
#define TILE_P 8
#define NBLK   (PD / TILE_P)   // 2048 CTAs

#define TWO_PI_OVER_64 0.09817477042468103870f

typedef unsigned long long u64;

// Packed, transposed weights: g_W[m][c2][o] = ( (WR[2c2][o],WR[2c2+1][o]), (WI[2c2][o],WI[2c2+1][o]) )
__device__ ulonglong2 g_W[MODES * 32 * 64];   // 512 KB

// ---------- packed f32x2 helpers ----------
__device__ __forceinline__ u64 pack2(float a, float b) {
    u64 r;
    asm("mov.b64 %0, {%1, %2};" : "=l"(r) : "f"(a), "f"(b));
    return r;
}
__device__ __forceinline__ void unpack2(u64 v, float &lo, float &hi) {
    asm("mov.b64 {%0, %1}, %2;" : "=f"(lo), "=f"(hi) : "l"(v));
}
__device__ __forceinline__ void fma2(u64 &d, u64 a, u64 b) {
    asm("fma.rn.f32x2 %0, %1, %2, %0;" : "+l"(d) : "l"(a), "l"(b));
}
__device__ __forceinline__ u64 add2(u64 a, u64 b) {
    u64 r;
    asm("add.rn.f32x2 %0, %1, %2;" : "=l"(r) : "l"(a), "l"(b));
    return r;
}
__device__ __forceinline__ float hadd(u64 v) {
    float lo, hi;
    unpack2(v, lo, hi);
    return lo + hi;
}

// =====================================================================
// One-time weight repack: w[c][o][m][2]  ->  g_W[m][c2][o]
// =====================================================================
__global__ void __launch_bounds__(256) w_pack(const float* __restrict__ w) {
    int idx = blockIdx.x * 256 + threadIdx.x;     // 0 .. 32767
    int m  = idx >> 11;
    int c2 = (idx >> 6) & 31;
    int o  = idx & 63;
    int c0 = 2 * c2;
    const float* b0 = w + ((((c0    ) * 64 + o) * MODES + m) << 1);
    const float* b1 = w + ((((c0 + 1) * 64 + o) * MODES + m) << 1);
    ulonglong2 v;
    v.x = pack2(b0[0], b1[0]);
    v.y = pack2(b0[1], b1[1]);
    g_W[idx] = v;
}

// =====================================================================
// Fused spectral conv. 256 threads, 8 pixels per CTA, 224 KB smem.
// smem layout (bytes):
//   [0      , 16384 ) F2  [mri][t]   packed (f,f)
//   [16384  , 32768 ) G2  [t][mri]   packed (g,g)
//   [32768  , 98304 ) Xft [mri][8p][64c] f32   (64 KB)
//   [98304  ,163840 ) Y   [mri][8p][64o] f32   (64 KB)
//   [163840 ,196608 ) W buf 0  [c2][o] ulonglong2
//   [196608 ,229376 ) W buf 1
// =====================================================================
__global__ void __launch_bounds__(256, 1) fused_spectral(const float* __restrict__ x,
                                                         float* __restrict__ out) {
    extern __shared__ __align__(16) char smem[];
    u64*        F2  = reinterpret_cast<u64*>(smem);
    u64*        G2  = reinterpret_cast<u64*>(smem + 16384);
    float*      Xsm = reinterpret_cast<float*>(smem + 32768);
    float*      Ysm = reinterpret_cast<float*>(smem + 98304);
    ulonglong2* Wb0 = reinterpret_cast<ulonglong2*>(smem + 163840);
    ulonglong2* Wb1 = reinterpret_cast<ulonglong2*>(smem + 196608);

    const int tid = threadIdx.x;
    const int p0  = blockIdx.x * TILE_P;

    // ---- DFT tables ----
    for (int idx = tid; idx < MRI * TD; idx += 256) {      // F2[mri][t]
        int mri = idx >> 6, t = idx & 63, m = mri >> 1;
        float s, c;
        sincosf((float)((m * t) & 63) * TWO_PI_OVER_64, &s, &c);
        float v = (mri & 1) ? -s : c;
        F2[idx] = pack2(v, v);
    }
    for (int idx = tid; idx < TD * MRI; idx += 256) {      // G2[t][mri]
        int t = idx >> 5, mri = idx & 31, m = mri >> 1;
        float s, c;
        sincosf((float)((m * t) & 63) * TWO_PI_OVER_64, &s, &c);
        float alpha = ((m == 0) ? 1.0f : 2.0f) * (1.0f / 64.0f);
        float v = (mri & 1) ? (-alpha * s) : (alpha * c);
        G2[idx] = pack2(v, v);
    }

    // ---- prefetch W for mode 0 (overlaps with stage 1 gmem reads) ----
    ulonglong2 wreg[8];
#pragma unroll
    for (int k = 0; k < 8; k++) wreg[k] = g_W[tid + k * 256];

    __syncthreads();   // tables ready

    // =============== Stage 1: truncated rfft into smem ===============
    {
        const int p  = tid >> 5;         // pixel within tile (warp-uniform)
        const int cp = tid & 31;         // channel pair
        const u64* xp = reinterpret_cast<const u64*>(x) + (long)(p0 + p) * 32 + cp;

        u64 acc[MRI];
#pragma unroll
        for (int i = 0; i < MRI; i++) acc[i] = 0ull;

#pragma unroll 4
        for (int t = 0; t < TD; t += 2) {
            u64 xv0 = xp[(long)t * (SCOL / 2)];
            u64 xv1 = xp[(long)(t + 1) * (SCOL / 2)];
#pragma unroll
            for (int mri = 0; mri < MRI; mri++) {
                ulonglong2 f = *reinterpret_cast<const ulonglong2*>(&F2[(mri << 6) + t]);
                fma2(acc[mri], xv0, f.x);
                fma2(acc[mri], xv1, f.y);
            }
        }
        u64* Xs64 = reinterpret_cast<u64*>(Xsm);
#pragma unroll
        for (int mri = 0; mri < MRI; mri++)
            Xs64[(mri * TILE_P + p) * 32 + cp] = acc[mri];
        // publish happens at the sync inside the first mode iteration
    }

    // =============== Stage 2: per-mode complex channel mix ===============
    {
        const int o   = tid & 63;
        const int px0 = (tid >> 6) * 2;            // warp-uniform pixel pair
        const u64* Xs64 = reinterpret_cast<const u64*>(Xsm);

        for (int m = 0; m < MODES; m++) {
            ulonglong2* Wc = (m & 1) ? Wb1 : Wb0;
#pragma unroll
            for (int k = 0; k < 8; k++) Wc[tid + k * 256] = wreg[k];
            __syncthreads();   // W visible; iter 0 also publishes Xsm

            if (m < MODES - 1) {
#pragma unroll
                for (int k = 0; k < 8; k++)
                    wreg[k] = g_W[(m + 1) * 2048 + tid + k * 256];
            }

            const u64* xR = Xs64 + ((2 * m)     * TILE_P + px0) * 32;
            const u64* xI = Xs64 + ((2 * m + 1) * TILE_P + px0) * 32;

            u64 aRR0 = 0, aII0 = 0, aRI0 = 0, aIR0 = 0;
            u64 aRR1 = 0, aII1 = 0, aRI1 = 0, aIR1 = 0;

#pragma unroll 8
            for (int c2 = 0; c2 < 32; c2 += 2) {
                ulonglong2 wv0 = Wc[(c2 << 6) + o];          // LDS.128
                ulonglong2 wv1 = Wc[((c2 + 1) << 6) + o];    // LDS.128
                ulonglong2 xr0 = *reinterpret_cast<const ulonglong2*>(&xR[c2]);
                ulonglong2 xi0 = *reinterpret_cast<const ulonglong2*>(&xI[c2]);
                ulonglong2 xr1 = *reinterpret_cast<const ulonglong2*>(&xR[32 + c2]);
                ulonglong2 xi1 = *reinterpret_cast<const ulonglong2*>(&xI[32 + c2]);

                fma2(aRR0, xr0.x, wv0.x); fma2(aII0, xi0.x, wv0.y);
                fma2(aRI0, xr0.x, wv0.y); fma2(aIR0, xi0.x, wv0.x);
                fma2(aRR0, xr0.y, wv1.x); fma2(aII0, xi0.y, wv1.y);
                fma2(aRI0, xr0.y, wv1.y); fma2(aIR0, xi0.y, wv1.x);

                fma2(aRR1, xr1.x, wv0.x); fma2(aII1, xi1.x, wv0.y);
                fma2(aRI1, xr1.x, wv0.y); fma2(aIR1, xi1.x, wv0.x);
                fma2(aRR1, xr1.y, wv1.x); fma2(aII1, xi1.y, wv1.y);
                fma2(aRI1, xr1.y, wv1.y); fma2(aIR1, xi1.y, wv1.x);
            }

            float yr0 = hadd(aRR0) - hadd(aII0);
            float yi0 = hadd(aRI0) + hadd(aIR0);
            float yr1 = hadd(aRR1) - hadd(aII1);
            float yi1 = hadd(aRI1) + hadd(aIR1);
            Ysm[((2 * m)     * TILE_P + px0)     * 64 + o] = yr0;
            Ysm[((2 * m + 1) * TILE_P + px0)     * 64 + o] = yi0;
            Ysm[((2 * m)     * TILE_P + px0 + 1) * 64 + o] = yr1;
            Ysm[((2 * m + 1) * TILE_P + px0 + 1) * 64 + o] = yi1;
        }
    }
    __syncthreads();   // Y complete

    // =============== Stage 3: truncated irfft from smem ===============
    {
        const int p  = tid >> 5;
        const int op = tid & 31;
        const u64* Ys64 = reinterpret_cast<const u64*>(Ysm);

        u64 y2[MRI];
#pragma unroll
        for (int mri = 0; mri < MRI; mri++)
            y2[mri] = Ys64[(mri * TILE_P + p) * 32 + op];

        u64* outp = reinterpret_cast<u64*>(out) + (long)(p0 + p) * 32 + op;
#pragma unroll 4
        for (int t = 0; t < TD; t += 2) {
            u64 aA0 = 0, aB0 = 0, aA1 = 0, aB1 = 0;   // 4 independent chains
#pragma unroll
            for (int mp = 0; mp < 16; mp += 2) {
                ulonglong2 g0a = *reinterpret_cast<const ulonglong2*>(&G2[(t << 5) + 2 * mp]);
                ulonglong2 g0b = *reinterpret_cast<const ulonglong2*>(&G2[(t << 5) + 2 * mp + 2]);
                ulonglong2 g1a = *reinterpret_cast<const ulonglong2*>(&G2[((t + 1) << 5) + 2 * mp]);
                ulonglong2 g1b = *reinterpret_cast<const ulonglong2*>(&G2[((t + 1) << 5) + 2 * mp + 2]);
                fma2(aA0, y2[2 * mp],     g0a.x);
                fma2(aA0, y2[2 * mp + 1], g0a.y);
                fma2(aB0, y2[2 * mp + 2], g0b.x);
                fma2(aB0, y2[2 * mp + 3], g0b.y);
                fma2(aA1, y2[2 * mp],     g1a.x);
                fma2(aA1, y2[2 * mp + 1], g1a.y);
                fma2(aB1, y2[2 * mp + 2], g1b.x);
                fma2(aB1, y2[2 * mp + 3], g1b.y);
            }
            outp[(long)t * (SCOL / 2)]       = add2(aA0, aB0);
            outp[(long)(t + 1) * (SCOL / 2)] = add2(aA1, aB1);
        }
    }
}

// =====================================================================
extern "C" void kernel_launch(void* const* d_in, const int* in_sizes, int n_in,
                              void* d_out, int out_size) {
    const float* x = (const float*)d_in[0];   // [64][1024][16][64] f32
    const float* w = (const float*)d_in[1];   // [64][64][16][2] f32
    float* out     = (float*)d_out;           // [64][1024][16][64] f32
    (void)in_sizes; (void)n_in; (void)out_size;

    cudaFuncSetAttribute(fused_spectral, cudaFuncAttributeMaxDynamicSharedMemorySize, 229376);

    w_pack<<<128, 256>>>(w);
    fused_spectral<<<NBLK, 256, 229376>>>(x, out);
}